// round 16
// baseline (speedup 1.0000x reference)
#include <cuda_runtime.h>
#include <cuda_bf16.h>
#include <math.h>

#define VD 32
#define KF 2048
#define NMAX 32768
#define LDT 80   // smem tile pitch in bf16 elements: 160B = 40 banks ≡ 8 (mod 32)
                 // -> uint2 fragment loads are conflict-free per half-warp phase

typedef unsigned int u32;
typedef unsigned long long u64;

// ---------------- device scratch (allocation-free rule) ----------------
__device__ float g_y[(size_t)NMAX * 64];
__device__ float g_w[(size_t)NMAX * VD];
// x images: [tok][2048] bf16 hi / lo, k-interleaved within each 16-group:
// pair order (0,1),(8,9),(2,3),(10,11),(4,5),(12,13),(6,7),(14,15)
__device__ __nv_bfloat16 g_xh[(size_t)NMAX * KF];
__device__ __nv_bfloat16 g_xl[(size_t)NMAX * KF];
// weight B-operand images, [n][k] bf16, same k-interleave
__device__ __nv_bfloat16 g_wgBh[64 * 2048];
__device__ __nv_bfloat16 g_wgBl[64 * 2048];
__device__ __nv_bfloat16 g_w1Bh[32 * 64 * 64];
__device__ __nv_bfloat16 g_w2Bh[32 * 64 * 64];
__device__ __nv_bfloat16 g_wgB2h[32 * 128 * 64];

// ---------------- helpers ----------------
__device__ __forceinline__ float sigmoidf_(float x) {
    return __fdividef(1.f, 1.f + __expf(-x));
}
__device__ __forceinline__ float eluf_(float x) { return x > 0.f ? x : (__expf(x) - 1.f); }

__device__ __forceinline__ float wsum_(float v) {
    #pragma unroll
    for (int o = 16; o > 0; o >>= 1) v += __shfl_xor_sync(0xffffffffu, v, o);
    return v;
}
__device__ __forceinline__ float wmax_(float v) {
    #pragma unroll
    for (int o = 16; o > 0; o >>= 1) v = fmaxf(v, __shfl_xor_sync(0xffffffffu, v, o));
    return v;
}

__device__ __forceinline__ void split2(float a, float b, u32& hi, u32& lo) {
    __nv_bfloat162 h = __floats2bfloat162_rn(a, b);
    u32 hu = *reinterpret_cast<u32*>(&h);
    float ra = a - __uint_as_float(hu << 16);
    float rb = b - __uint_as_float(hu & 0xffff0000u);
    __nv_bfloat162 l = __floats2bfloat162_rn(ra, rb);
    hi = hu; lo = *reinterpret_cast<u32*>(&l);
}
__device__ __forceinline__ u32 pack_bf2(float a, float b) {
    __nv_bfloat162 h = __floats2bfloat162_rn(a, b);
    return *reinterpret_cast<u32*>(&h);
}
__device__ __forceinline__ float lo16f_(u32 u) { return __uint_as_float(u << 16); }
__device__ __forceinline__ float hi16f_(u32 u) { return __uint_as_float(u & 0xffff0000u); }

// interleaved position of even k-pair start c (element offset within row)
__device__ __forceinline__ int permc(int c) {
    return (c & ~15) | (((c & 7) >> 1) << 2) | (((c >> 3) & 1) << 1);
}

// cp.async 16B: global -> shared, no register transit
__device__ __forceinline__ void cp16(const char* smem_dst, const void* gsrc) {
    u32 d = (u32)__cvta_generic_to_shared(smem_dst);
    asm volatile("cp.async.cg.shared.global [%0], [%1], 16;" :: "r"(d), "l"(gsrc));
}
__device__ __forceinline__ void cp_commit_wait() {
    asm volatile("cp.async.commit_group;" ::: "memory");
    asm volatile("cp.async.wait_group 0;" ::: "memory");
}

// mma.sync m16n8k16 bf16 -> f32 accumulate
__device__ __forceinline__ void mma_(float (&d)[4], u32 a0, u32 a1, u32 a2, u32 a3,
                                     u32 b0, u32 b1) {
    asm volatile(
        "mma.sync.aligned.m16n8k16.row.col.f32.bf16.bf16.f32 "
        "{%0,%1,%2,%3}, {%4,%5,%6,%7}, {%8,%9}, {%0,%1,%2,%3};"
        : "+f"(d[0]), "+f"(d[1]), "+f"(d[2]), "+f"(d[3])
        : "r"(a0), "r"(a1), "r"(a2), "r"(a3), "r"(b0), "r"(b1));
}

// single-term K=64 GEMM, A+B in smem (interleaved layout, uint2 frags)
template<int NT>
__device__ __forceinline__ void gemm1t_p(const char* sm, int Aof, int Bof,
                                         int r0, int g, int tg, float (&acc)[NT][4]) {
    #pragma unroll
    for (int ks = 0; ks < 4; ks++) {
        int ao = ks * 16 + tg * 4;
        uint2 aA = *(const uint2*)(sm + Aof + ((r0 + g) * LDT + ao) * 2);
        uint2 aB = *(const uint2*)(sm + Aof + ((r0 + g + 8) * LDT + ao) * 2);
        #pragma unroll
        for (int nt = 0; nt < NT; nt++) {
            uint2 b = *(const uint2*)(sm + Bof + ((nt * 8 + g) * LDT + ao) * 2);
            mma_(acc[nt], aA.x, aB.x, aA.y, aB.y, b.x, b.y);
        }
    }
}

// single-term K=64 GEMM, A in registers (af[16], 4 per k-slice)
template<int NT>
__device__ __forceinline__ void gemmR(const char* sm, int Bof, const u32 (&af)[16],
                                      int g, int tg, float (&acc)[NT][4]) {
    #pragma unroll
    for (int ks = 0; ks < 4; ks++) {
        int ao = ks * 16 + tg * 4;
        #pragma unroll
        for (int nt = 0; nt < NT; nt++) {
            uint2 b = *(const uint2*)(sm + Bof + ((nt * 8 + g) * LDT + ao) * 2);
            mma_(acc[nt], af[4 * ks], af[4 * ks + 1], af[4 * ks + 2], af[4 * ks + 3], b.x, b.y);
        }
    }
}

// 3-term K=64 GEMM (hi/lo), interleaved layout
template<int NT>
__device__ __forceinline__ void gemm3p(const char* sm, int AHI, int ALO, int BHI, int BLO,
                                       int r0, int g, int tg, float (&acc)[NT][4]) {
    #pragma unroll
    for (int ks = 0; ks < 4; ks++) {
        int ao = ks * 16 + tg * 4;
        uint2 ahA = *(const uint2*)(sm + AHI + ((r0 + g) * LDT + ao) * 2);
        uint2 ahB = *(const uint2*)(sm + AHI + ((r0 + g + 8) * LDT + ao) * 2);
        uint2 alA = *(const uint2*)(sm + ALO + ((r0 + g) * LDT + ao) * 2);
        uint2 alB = *(const uint2*)(sm + ALO + ((r0 + g + 8) * LDT + ao) * 2);
        #pragma unroll
        for (int nt = 0; nt < NT; nt++) {
            uint2 b = *(const uint2*)(sm + BHI + ((nt * 8 + g) * LDT + ao) * 2);
            mma_(acc[nt], ahA.x, ahB.x, ahA.y, ahB.y, b.x, b.y);
        }
        #pragma unroll
        for (int nt = 0; nt < NT; nt++) {
            uint2 b = *(const uint2*)(sm + BLO + ((nt * 8 + g) * LDT + ao) * 2);
            mma_(acc[nt], ahA.x, ahB.x, ahA.y, ahB.y, b.x, b.y);
        }
        #pragma unroll
        for (int nt = 0; nt < NT; nt++) {
            uint2 b = *(const uint2*)(sm + BHI + ((nt * 8 + g) * LDT + ao) * 2);
            mma_(acc[nt], alA.x, alB.x, alA.y, alB.y, b.x, b.y);
        }
    }
}

// stage 128x64 bf16 image tile via cp.async (interleave baked into image)
__device__ __forceinline__ void stage_x_async(char* sm, int DSTo,
        const __nv_bfloat16* __restrict__ img, int tok0, int kbase, int tid) {
    #pragma unroll
    for (int p = 0; p < 4; p++) {
        int idx = tid + p * 256;
        int row = idx >> 3, ch = idx & 7;
        cp16(sm + DSTo + (row * LDT + ch * 8) * 2,
             img + (size_t)(tok0 + row) * KF + kbase + ch * 8);
    }
}

// stage 64x64 bf16 weight tile via cp.async (perm baked into global image)
__device__ __forceinline__ void stage_w64_a(char* sm, int DSTo,
        const __nv_bfloat16* __restrict__ src, int pitch, int tid) {
    int row = tid >> 2, part = tid & 3;
    #pragma unroll
    for (int q = 0; q < 2; q++) {
        int col = (part * 2 + q) * 8;
        cp16(sm + DSTo + (row * LDT + col) * 2, &src[(size_t)row * pitch + col]);
    }
}
__device__ __forceinline__ void stage_w128_a(char* sm, int DSTo,
        const __nv_bfloat16* __restrict__ src, int tid) {
    int row = tid >> 1, part = tid & 1;
    #pragma unroll
    for (int q = 0; q < 4; q++) {
        int col = (part * 4 + q) * 8;
        cp16(sm + DSTo + (row * LDT + col) * 2, &src[(size_t)row * 64 + col]);
    }
}

// build next-GEMM A-fragments (registers) from accumulators (+bias, opt elu)
__device__ __forceinline__ void frag_from_acc(u32 (&af)[16], const float (&acc)[8][4],
        const float* __restrict__ bias, int tg, bool do_elu) {
    #pragma unroll
    for (int ks = 0; ks < 4; ks++) {
        int c = ks * 16 + tg * 2, c8 = c + 8;
        float b0 = bias[c], b1 = bias[c + 1], b2 = bias[c8], b3 = bias[c8 + 1];
        float v00 = acc[2 * ks][0] + b0, v01 = acc[2 * ks][1] + b1;
        float v10 = acc[2 * ks][2] + b0, v11 = acc[2 * ks][3] + b1;
        float w00 = acc[2 * ks + 1][0] + b2, w01 = acc[2 * ks + 1][1] + b3;
        float w10 = acc[2 * ks + 1][2] + b2, w11 = acc[2 * ks + 1][3] + b3;
        if (do_elu) {
            v00 = eluf_(v00); v01 = eluf_(v01); v10 = eluf_(v10); v11 = eluf_(v11);
            w00 = eluf_(w00); w01 = eluf_(w01); w10 = eluf_(w10); w11 = eluf_(w11);
        }
        af[4 * ks]     = pack_bf2(v00, v01);   // row g,   k c,c+1
        af[4 * ks + 1] = pack_bf2(v10, v11);   // row g+8
        af[4 * ks + 2] = pack_bf2(w00, w01);   // row g,   k c8,c8+1
        af[4 * ks + 3] = pack_bf2(w10, w11);   // row g+8
    }
}

// ============================================================
// kPrepX: x fp32 -> interleaved bf16 hi/lo images. One 16-col group per thread.
// pair order within group: (0,1),(8,9),(2,3),(10,11),(4,5),(12,13),(6,7),(14,15)
// ============================================================
__global__ void __launch_bounds__(256) kPrepX(const float* __restrict__ x) {
    int idx = blockIdx.x * 256 + threadIdx.x;
    int tok = idx >> 7, grp = idx & 127;
    const float* xr = x + (size_t)tok * KF + grp * 16;
    float4 f0 = *(const float4*)(xr);
    float4 f1 = *(const float4*)(xr + 4);
    float4 f2 = *(const float4*)(xr + 8);
    float4 f3 = *(const float4*)(xr + 12);
    u32 h[8], l[8];
    split2(f0.x, f0.y, h[0], l[0]);   // k0,1   -> pos 0
    split2(f2.x, f2.y, h[1], l[1]);   // k8,9   -> pos 2
    split2(f0.z, f0.w, h[2], l[2]);   // k2,3   -> pos 4
    split2(f2.z, f2.w, h[3], l[3]);   // k10,11 -> pos 6
    split2(f1.x, f1.y, h[4], l[4]);   // k4,5   -> pos 8
    split2(f3.x, f3.y, h[5], l[5]);   // k12,13 -> pos 10
    split2(f1.z, f1.w, h[6], l[6]);   // k6,7   -> pos 12
    split2(f3.z, f3.w, h[7], l[7]);   // k14,15 -> pos 14
    size_t base = (size_t)tok * KF + grp * 16;
    *(uint4*)&g_xh[base]     = make_uint4(h[0], h[1], h[2], h[3]);
    *(uint4*)&g_xh[base + 8] = make_uint4(h[4], h[5], h[6], h[7]);
    *(uint4*)&g_xl[base]     = make_uint4(l[0], l[1], l[2], l[3]);
    *(uint4*)&g_xl[base + 8] = make_uint4(l[4], l[5], l[6], l[7]);
}

// ============================================================
// kPrepW: transpose + split weight B-operands into interleaved [n][k] images
// ============================================================
__device__ __forceinline__ void store8hl_p(__nv_bfloat16* hiA, __nv_bfloat16* loA,
                                           size_t rowbase, int j, const float f[8]) {
    int base = (j >> 1) * 16 + ((j & 1) << 1);
    #pragma unroll
    for (int p = 0; p < 4; p++) {
        u32 h, l;
        split2(f[2 * p], f[2 * p + 1], h, l);
        *(u32*)&hiA[rowbase + base + 4 * p] = h;
        *(u32*)&loA[rowbase + base + 4 * p] = l;
    }
}
__device__ __forceinline__ void store8h_p(__nv_bfloat16* hiA, size_t rowbase, int j,
                                          const float f[8]) {
    int base = (j >> 1) * 16 + ((j & 1) << 1);
    #pragma unroll
    for (int p = 0; p < 4; p++)
        *(u32*)&hiA[rowbase + base + 4 * p] = pack_bf2(f[2 * p], f[2 * p + 1]);
}

__global__ void __launch_bounds__(256) kPrepW(
    const float* __restrict__ wgW1, const float* __restrict__ wgWs,
    const float* __restrict__ vW1, const float* __restrict__ vW2,
    const float* __restrict__ vWg) {
    int id = blockIdx.x * 256 + threadIdx.x;
    float f[8];
    if (id < 16384) {                    // wgB: [64 n][2048 k] hi/lo
        int j = id & 7, n = (id >> 3) & 63, c = id >> 9;
        int k0 = c * 64 + j * 8;
        #pragma unroll
        for (int kk = 0; kk < 8; kk++)
            f[kk] = (n < 32) ? wgW1[(size_t)(k0 + kk) * 32 + n]
                             : wgWs[(size_t)(k0 + kk) * 32 + (n - 32)];
        store8hl_p(g_wgBh, g_wgBl, (size_t)n * 2048 + c * 64, j, f);
    } else if (id < 32768) {             // vW1: [v][64 n][64 k]
        id -= 16384;
        int j = id & 7, n = (id >> 3) & 63, v = id >> 9;
        #pragma unroll
        for (int kk = 0; kk < 8; kk++)
            f[kk] = vW1[((size_t)v * 64 + j * 8 + kk) * 64 + n];
        store8h_p(g_w1Bh, ((size_t)v * 64 + n) * 64, j, f);
    } else if (id < 49152) {             // vW2
        id -= 32768;
        int j = id & 7, n = (id >> 3) & 63, v = id >> 9;
        #pragma unroll
        for (int kk = 0; kk < 8; kk++)
            f[kk] = vW2[((size_t)v * 64 + j * 8 + kk) * 64 + n];
        store8h_p(g_w2Bh, ((size_t)v * 64 + n) * 64, j, f);
    } else if (id < 81920) {             // vWg: [v][128 n][64 k]
        id -= 49152;
        int j = id & 7, n = (id >> 3) & 127, v = id >> 10;
        #pragma unroll
        for (int kk = 0; kk < 8; kk++)
            f[kk] = vWg[((size_t)v * 64 + j * 8 + kk) * 128 + n];
        store8h_p(g_wgB2h, ((size_t)v * 128 + n) * 64, j, f);
    }
}

// ============================================================
// kA1m: Y[N,64] = flat[N,2048] @ [W1|Ws] (+bias) via mma.sync (3-term)
// All staging via cp.async from prepped images.
// ============================================================
#define A1_XHI 0
#define A1_XLO 20480
#define A1_BH  40960
#define A1_BL  51200
#define A1_SMEM 61440

__global__ void __launch_bounds__(256, 2) kA1m(
    const float* __restrict__ b1, const float* __restrict__ bs) {
    extern __shared__ __align__(16) char sm[];
    const int tid = threadIdx.x, lane = tid & 31;
    const int warp = tid >> 5, g = lane >> 2, tg = lane & 3;
    const int r0 = warp * 16, tok0 = blockIdx.x * 128;

    float acc[8][4];
    #pragma unroll
    for (int nt = 0; nt < 8; nt++)
        acc[nt][0] = acc[nt][1] = acc[nt][2] = acc[nt][3] = 0.f;

    for (int kc = 0; kc < 32; kc++) {
        stage_w64_a(sm, A1_BH, g_wgBh + kc * 64, 2048, tid);
        stage_w64_a(sm, A1_BL, g_wgBl + kc * 64, 2048, tid);
        stage_x_async(sm, A1_XHI, g_xh, tok0, kc * 64, tid);
        stage_x_async(sm, A1_XLO, g_xl, tok0, kc * 64, tid);
        cp_commit_wait();
        __syncthreads();
        gemm3p<8>(sm, A1_XHI, A1_XLO, A1_BH, A1_BL, r0, g, tg, acc);
        __syncthreads();
    }

    #pragma unroll
    for (int nt = 0; nt < 8; nt++) {
        int c = nt * 8 + tg * 2;
        float bb0 = (c < 32) ? b1[c] : bs[c - 32];
        float bb1 = (c + 1 < 32) ? b1[c + 1] : bs[c + 1 - 32];
        float* yA = &g_y[(size_t)(tok0 + r0 + g) * 64 + c];
        float* yB = &g_y[(size_t)(tok0 + r0 + g + 8) * 64 + c];
        yA[0] = acc[nt][0] + bb0; yA[1] = acc[nt][1] + bb1;
        yB[0] = acc[nt][2] + bb0; yB[1] = acc[nt][3] + bb1;
    }
}

// ============================================================
// kA2: per-token tail of the weight GRN (fp32, cheap)
// ============================================================
__global__ void __launch_bounds__(256) kA2(
    const float* __restrict__ W2, const float* __restrict__ b2,
    const float* __restrict__ Wg, const float* __restrict__ bg,
    const float* __restrict__ gam, const float* __restrict__ bet, int N) {
    __shared__ float W2s[32 * 33];
    __shared__ float Wgs[32 * 64];
    const int tid = threadIdx.x;
    for (int i = tid; i < 1024; i += 256) W2s[(i >> 5) * 33 + (i & 31)] = W2[i];
    for (int i = tid; i < 2048; i += 256) Wgs[i] = Wg[i];
    __syncthreads();

    const int lane = tid & 31, warp = tid >> 5;
    const int tok = blockIdx.x * 8 + warp;
    if (tok >= N) return;

    const float* y = &g_y[(size_t)tok * 64];
    float h = eluf_(y[lane]);
    float skip = y[32 + lane];

    float t = b2[lane];
    #pragma unroll
    for (int i = 0; i < 32; i++)
        t = fmaf(__shfl_sync(0xffffffffu, h, i), W2s[i * 33 + lane], t);

    float ga = bg[lane], gb = bg[32 + lane];
    #pragma unroll
    for (int i = 0; i < 32; i++) {
        float tv = __shfl_sync(0xffffffffu, t, i);
        ga = fmaf(tv, Wgs[i * 64 + lane], ga);
        gb = fmaf(tv, Wgs[i * 64 + 32 + lane], gb);
    }

    float z = skip + ga * sigmoidf_(gb);
    float m = wsum_(z) * (1.f / 32.f);
    float d = z - m;
    float var = wsum_(d * d) * (1.f / 32.f);
    float zn = d * rsqrtf(var + 1e-5f) * gam[lane] + bet[lane];

    float mx = wmax_(zn);
    float e = __expf(zn - mx);
    float se = wsum_(e);
    g_w[(size_t)tok * VD + lane] = e / se;
}

// ============================================================
// kBm: per-variable GRNs + combine. Register-chained GEMMs (2 syncs/var),
//      conflict-free uint2 fragment loads (LDT=80), smem-x epilogue,
//      ALL staging via cp.async from prepped images.
// ============================================================
#define KB_XHI  0
#define KB_XLO  20480
#define KB_W1   40960
#define KB_W2   51200
#define KB_WG   61440
#define KB_BIAS 81920
#define KB_SMEM (81920 + 2048)

__global__ void __launch_bounds__(256, 2) kBm(
    const float* __restrict__ vb1, const float* __restrict__ vb2,
    const float* __restrict__ vbg, const float* __restrict__ vgam,
    const float* __restrict__ vbet, float* __restrict__ out) {
    extern __shared__ __align__(16) char sm[];
    float* b1s  = (float*)(sm + KB_BIAS);        // 64
    float* b2s  = b1s + 64;                      // 64
    float* bgs  = b2s + 64;                      // 128
    float* gams = bgs + 128;                     // 64
    float* bets = gams + 64;                     // 64
    float* wvS  = bets + 64;                     // 128

    const int tid = threadIdx.x, lane = tid & 31;
    const int warp = tid >> 5, g = lane >> 2, tg = lane & 3;
    const int r0 = warp * 16, tok0 = blockIdx.x * 128;

    float oacc[2][16];
    #pragma unroll
    for (int s = 0; s < 2; s++)
        #pragma unroll
        for (int i = 0; i < 16; i++) oacc[s][i] = 0.f;

    for (int v = 0; v < VD; v++) {
        // ---- stage (everything via cp.async) ----
        stage_w64_a(sm, KB_W1, g_w1Bh + (size_t)v * 4096, 64, tid);
        stage_w64_a(sm, KB_W2, g_w2Bh + (size_t)v * 4096, 64, tid);
        stage_w128_a(sm, KB_WG, g_wgB2h + (size_t)v * 8192, tid);
        stage_x_async(sm, KB_XHI, g_xh, tok0, v * 64, tid);
        stage_x_async(sm, KB_XLO, g_xl, tok0, v * 64, tid);
        if (tid < 64) {
            b1s[tid]  = vb1[(size_t)v * 64 + tid];
            b2s[tid]  = vb2[(size_t)v * 64 + tid];
            gams[tid] = vgam[(size_t)v * 64 + tid];
            bets[tid] = vbet[(size_t)v * 64 + tid];
        } else if (tid < 192) {
            bgs[tid - 64] = vbg[(size_t)v * 128 + (tid - 64)];
        }
        if (tid < 128) wvS[tid] = g_w[(size_t)(tok0 + tid) * VD + v];
        cp_commit_wait();
        __syncthreads();

        // ---- GEMM1: X@W1 -> elu(+b1) -> register fragments ----
        u32 hf[16];
        {
            float acc[8][4];
            #pragma unroll
            for (int nt = 0; nt < 8; nt++)
                acc[nt][0] = acc[nt][1] = acc[nt][2] = acc[nt][3] = 0.f;
            gemm1t_p<8>(sm, KB_XHI, KB_W1, r0, g, tg, acc);
            frag_from_acc(hf, acc, b1s, tg, true);
        }

        // ---- GEMM2: H1@W2 (+b2) -> register fragments ----
        {
            float acc[8][4];
            #pragma unroll
            for (int nt = 0; nt < 8; nt++)
                acc[nt][0] = acc[nt][1] = acc[nt][2] = acc[nt][3] = 0.f;
            gemmR<8>(sm, KB_W2, hf, g, tg, acc);
            frag_from_acc(hf, acc, b2s, tg, false);
        }

        // ---- GEMM3: H2@Wg (N=128) + epilogue (x from smem hi+lo) ----
        {
            float acc3[16][4];
            #pragma unroll
            for (int nt = 0; nt < 16; nt++)
                acc3[nt][0] = acc3[nt][1] = acc3[nt][2] = acc3[nt][3] = 0.f;
            gemmR<16>(sm, KB_WG, hf, g, tg, acc3);

            #pragma unroll
            for (int sel = 0; sel < 2; sel++) {
                const int row = r0 + g + sel * 8;
                const int di = sel * 2;
                float vals[16];
                float s1 = 0.f, s2 = 0.f;
                #pragma unroll
                for (int i = 0; i < 8; i++) {
                    int c = i * 8 + tg * 2;
                    int pos = permc(c);
                    u32 xh = *(const u32*)(sm + KB_XHI + (row * LDT + pos) * 2);
                    u32 xl = *(const u32*)(sm + KB_XLO + (row * LDT + pos) * 2);
                    float x0 = lo16f_(xh) + lo16f_(xl);
                    float x1 = hi16f_(xh) + hi16f_(xl);
                    float aL = acc3[i][di] + bgs[c];
                    float aR = acc3[i][di + 1] + bgs[c + 1];
                    float gL = acc3[8 + i][di] + bgs[64 + c];
                    float gR = acc3[8 + i][di + 1] + bgs[64 + c + 1];
                    float v0 = x0 + aL * sigmoidf_(gL);
                    float v1 = x1 + aR * sigmoidf_(gR);
                    vals[2 * i] = v0; vals[2 * i + 1] = v1;
                    s1 += v0 + v1;
                    s2 += v0 * v0 + v1 * v1;
                }
                s1 += __shfl_xor_sync(0xffffffffu, s1, 1);
                s1 += __shfl_xor_sync(0xffffffffu, s1, 2);
                s2 += __shfl_xor_sync(0xffffffffu, s2, 1);
                s2 += __shfl_xor_sync(0xffffffffu, s2, 2);
                float m = s1 * (1.f / 64.f);
                float var = fmaxf(s2 * (1.f / 64.f) - m * m, 0.f);
                float rs = rsqrtf(var + 1e-5f);
                float wv = wvS[row];
                #pragma unroll
                for (int i = 0; i < 8; i++) {
                    int c = i * 8 + tg * 2;
                    float pv0 = (vals[2 * i] - m) * rs * gams[c] + bets[c];
                    float pv1 = (vals[2 * i + 1] - m) * rs * gams[c + 1] + bets[c + 1];
                    oacc[sel][2 * i]     = fmaf(wv, pv0, oacc[sel][2 * i]);
                    oacc[sel][2 * i + 1] = fmaf(wv, pv1, oacc[sel][2 * i + 1]);
                }
            }
        }
        __syncthreads();   // done reading tiles before next stage overwrites
    }

    #pragma unroll
    for (int sel = 0; sel < 2; sel++) {
        int row = r0 + g + sel * 8;
        float* op = &out[(size_t)(tok0 + row) * 64];
        #pragma unroll
        for (int i = 0; i < 8; i++) {
            int c = i * 8 + tg * 2;
            *(float2*)&op[c] = make_float2(oacc[sel][2 * i], oacc[sel][2 * i + 1]);
        }
    }
}

// ============================================================
extern "C" void kernel_launch(void* const* d_in, const int* in_sizes, int n_in,
                              void* d_out, int out_size) {
    const float* x     = (const float*)d_in[0];
    const float* wgW1  = (const float*)d_in[1];
    const float* wgb1  = (const float*)d_in[2];
    const float* wgW2  = (const float*)d_in[3];
    const float* wgb2  = (const float*)d_in[4];
    const float* wgWg  = (const float*)d_in[5];
    const float* wgbg  = (const float*)d_in[6];
    const float* wgWs  = (const float*)d_in[7];
    const float* wgbs  = (const float*)d_in[8];
    const float* wggam = (const float*)d_in[9];
    const float* wgbet = (const float*)d_in[10];
    const float* vW1   = (const float*)d_in[11];
    const float* vb1   = (const float*)d_in[12];
    const float* vW2   = (const float*)d_in[13];
    const float* vb2   = (const float*)d_in[14];
    const float* vWg   = (const float*)d_in[15];
    const float* vbg   = (const float*)d_in[16];
    const float* vgam  = (const float*)d_in[17];
    const float* vbet  = (const float*)d_in[18];
    float* out = (float*)d_out;

    int N = in_sizes[0] / KF;  // 32768

    kPrepX<<<(N * 128) / 256, 256>>>(x);
    kPrepW<<<320, 256>>>(wgW1, wgWs, vW1, vW2, vWg);

    cudaFuncSetAttribute(kA1m, cudaFuncAttributeMaxDynamicSharedMemorySize, A1_SMEM);
    kA1m<<<N / 128, 256, A1_SMEM>>>(wgb1, wgbs);

    kA2<<<(N + 7) / 8, 256>>>(wgW2, wgb2, wgWg, wgbg, wggam, wgbet, N);

    cudaFuncSetAttribute(kBm, cudaFuncAttributeMaxDynamicSharedMemorySize, KB_SMEM);
    kBm<<<N / 128, 256, KB_SMEM>>>(vb1, vb2, vbg, vgam, vbet, out);
}

// round 17
// speedup vs baseline: 1.3083x; 1.3083x over previous
#include <cuda_runtime.h>
#include <cuda_bf16.h>
#include <math.h>

#define VD 32
#define KF 2048
#define NMAX 32768
#define LDT 80   // bf16 weight-tile pitch: 160B = 40 banks ≡ 8 (mod 32) — conflict-free uint2
#define LDX 72   // fp32 x-tile pitch: 288B ≡ 8 banks (mod 32) — conflict-free LDS.64

typedef unsigned int u32;
typedef unsigned long long u64;

// ---------------- device scratch (allocation-free rule) ----------------
__device__ float g_y[(size_t)NMAX * 64];
__device__ float g_w[(size_t)NMAX * VD];
// weight B-operand images, [n][k] bf16, k-interleaved within each 16-slice:
// pos(k) = (k>>4)*16 + 4*((k&7)>>1) + 2*((k>>3)&1) + (k&1)
__device__ __nv_bfloat16 g_wgBh[64 * 2048];
__device__ __nv_bfloat16 g_wgBl[64 * 2048];
__device__ __nv_bfloat16 g_w1Bh[32 * 64 * 64];
__device__ __nv_bfloat16 g_w2Bh[32 * 64 * 64];
__device__ __nv_bfloat16 g_wgB2h[32 * 128 * 64];

// ---------------- helpers ----------------
__device__ __forceinline__ float sigmoidf_(float x) {
    return __fdividef(1.f, 1.f + __expf(-x));
}
__device__ __forceinline__ float eluf_(float x) { return x > 0.f ? x : (__expf(x) - 1.f); }

__device__ __forceinline__ float wsum_(float v) {
    #pragma unroll
    for (int o = 16; o > 0; o >>= 1) v += __shfl_xor_sync(0xffffffffu, v, o);
    return v;
}
__device__ __forceinline__ float wmax_(float v) {
    #pragma unroll
    for (int o = 16; o > 0; o >>= 1) v = fmaxf(v, __shfl_xor_sync(0xffffffffu, v, o));
    return v;
}

__device__ __forceinline__ void split2(float a, float b, u32& hi, u32& lo) {
    __nv_bfloat162 h = __floats2bfloat162_rn(a, b);
    u32 hu = *reinterpret_cast<u32*>(&h);
    float ra = a - __uint_as_float(hu << 16);
    float rb = b - __uint_as_float(hu & 0xffff0000u);
    __nv_bfloat162 l = __floats2bfloat162_rn(ra, rb);
    hi = hu; lo = *reinterpret_cast<u32*>(&l);
}
__device__ __forceinline__ u32 pack_bf2(float a, float b) {
    __nv_bfloat162 h = __floats2bfloat162_rn(a, b);
    return *reinterpret_cast<u32*>(&h);
}

// cp.async 16B: global -> shared, no register transit
__device__ __forceinline__ void cp16(const char* smem_dst, const void* gsrc) {
    u32 d = (u32)__cvta_generic_to_shared(smem_dst);
    asm volatile("cp.async.cg.shared.global [%0], [%1], 16;" :: "r"(d), "l"(gsrc));
}
__device__ __forceinline__ void cp_commit_wait() {
    asm volatile("cp.async.commit_group;" ::: "memory");
    asm volatile("cp.async.wait_group 0;" ::: "memory");
}

// mma.sync m16n8k16 bf16 -> f32 accumulate
__device__ __forceinline__ void mma_(float (&d)[4], u32 a0, u32 a1, u32 a2, u32 a3,
                                     u32 b0, u32 b1) {
    asm volatile(
        "mma.sync.aligned.m16n8k16.row.col.f32.bf16.bf16.f32 "
        "{%0,%1,%2,%3}, {%4,%5,%6,%7}, {%8,%9}, {%0,%1,%2,%3};"
        : "+f"(d[0]), "+f"(d[1]), "+f"(d[2]), "+f"(d[3])
        : "r"(a0), "r"(a1), "r"(a2), "r"(a3), "r"(b0), "r"(b1));
}

// single-term K=64 GEMM, A built on the fly from fp32 x tile, B in bf16 smem
template<int NT>
__device__ __forceinline__ void gemm1x(const char* sm, int Xof, int Bof,
                                       int r0, int g, int tg, float (&acc)[NT][4]) {
    const float* xb = (const float*)(sm + Xof);
    #pragma unroll
    for (int ks = 0; ks < 4; ks++) {
        int c = ks * 16 + tg * 2;
        float2 v0 = *(const float2*)&xb[(r0 + g) * LDX + c];
        float2 v1 = *(const float2*)&xb[(r0 + g + 8) * LDX + c];
        float2 v2 = *(const float2*)&xb[(r0 + g) * LDX + c + 8];
        float2 v3 = *(const float2*)&xb[(r0 + g + 8) * LDX + c + 8];
        u32 a0 = pack_bf2(v0.x, v0.y), a1 = pack_bf2(v1.x, v1.y);
        u32 a2 = pack_bf2(v2.x, v2.y), a3 = pack_bf2(v3.x, v3.y);
        int ao = ks * 16 + tg * 4;
        #pragma unroll
        for (int nt = 0; nt < NT; nt++) {
            uint2 b = *(const uint2*)(sm + Bof + ((nt * 8 + g) * LDT + ao) * 2);
            mma_(acc[nt], a0, a1, a2, a3, b.x, b.y);
        }
    }
}

// 3-term K=64 GEMM: A hi/lo built on the fly from fp32 x tile, B hi/lo in bf16 smem
template<int NT>
__device__ __forceinline__ void gemm3x(const char* sm, int Xof, int BHI, int BLO,
                                       int r0, int g, int tg, float (&acc)[NT][4]) {
    const float* xb = (const float*)(sm + Xof);
    #pragma unroll
    for (int ks = 0; ks < 4; ks++) {
        int c = ks * 16 + tg * 2;
        float2 v0 = *(const float2*)&xb[(r0 + g) * LDX + c];
        float2 v1 = *(const float2*)&xb[(r0 + g + 8) * LDX + c];
        float2 v2 = *(const float2*)&xb[(r0 + g) * LDX + c + 8];
        float2 v3 = *(const float2*)&xb[(r0 + g + 8) * LDX + c + 8];
        u32 ah0, al0, ah1, al1, ah2, al2, ah3, al3;
        split2(v0.x, v0.y, ah0, al0);
        split2(v1.x, v1.y, ah1, al1);
        split2(v2.x, v2.y, ah2, al2);
        split2(v3.x, v3.y, ah3, al3);
        int ao = ks * 16 + tg * 4;
        #pragma unroll
        for (int nt = 0; nt < NT; nt++) {
            uint2 b = *(const uint2*)(sm + BHI + ((nt * 8 + g) * LDT + ao) * 2);
            mma_(acc[nt], ah0, ah1, ah2, ah3, b.x, b.y);
        }
        #pragma unroll
        for (int nt = 0; nt < NT; nt++) {
            uint2 b = *(const uint2*)(sm + BLO + ((nt * 8 + g) * LDT + ao) * 2);
            mma_(acc[nt], ah0, ah1, ah2, ah3, b.x, b.y);
        }
        #pragma unroll
        for (int nt = 0; nt < NT; nt++) {
            uint2 b = *(const uint2*)(sm + BHI + ((nt * 8 + g) * LDT + ao) * 2);
            mma_(acc[nt], al0, al1, al2, al3, b.x, b.y);
        }
    }
}

// single-term K=64 GEMM, A in registers (af[16], 4 per k-slice)
template<int NT>
__device__ __forceinline__ void gemmR(const char* sm, int Bof, const u32 (&af)[16],
                                      int g, int tg, float (&acc)[NT][4]) {
    #pragma unroll
    for (int ks = 0; ks < 4; ks++) {
        int ao = ks * 16 + tg * 4;
        #pragma unroll
        for (int nt = 0; nt < NT; nt++) {
            uint2 b = *(const uint2*)(sm + Bof + ((nt * 8 + g) * LDT + ao) * 2);
            mma_(acc[nt], af[4 * ks], af[4 * ks + 1], af[4 * ks + 2], af[4 * ks + 3], b.x, b.y);
        }
    }
}

// stage 128x64 fp32 x tile via cp.async (natural order, pitch LDX)
__device__ __forceinline__ void stage_xf32(char* sm, int DSTo,
        const float* __restrict__ x, int tok0, int kbase, int tid) {
    float* xb = (float*)(sm + DSTo);
    #pragma unroll
    for (int p = 0; p < 8; p++) {
        int idx = tid + p * 256;
        int row = idx >> 4, c4 = (idx & 15) * 4;
        cp16((char*)&xb[row * LDX + c4],
             x + (size_t)(tok0 + row) * KF + kbase + c4);
    }
}

// stage 64x64 bf16 weight tile via cp.async (perm baked into global image)
__device__ __forceinline__ void stage_w64_a(char* sm, int DSTo,
        const __nv_bfloat16* __restrict__ src, int pitch, int tid) {
    int row = tid >> 2, part = tid & 3;
    #pragma unroll
    for (int q = 0; q < 2; q++) {
        int col = (part * 2 + q) * 8;
        cp16(sm + DSTo + (row * LDT + col) * 2, &src[(size_t)row * pitch + col]);
    }
}
__device__ __forceinline__ void stage_w128_a(char* sm, int DSTo,
        const __nv_bfloat16* __restrict__ src, int tid) {
    int row = tid >> 1, part = tid & 1;
    #pragma unroll
    for (int q = 0; q < 4; q++) {
        int col = (part * 4 + q) * 8;
        cp16(sm + DSTo + (row * LDT + col) * 2, &src[(size_t)row * 64 + col]);
    }
}

// build next-GEMM A-fragments (registers) from accumulators (+bias, opt elu)
__device__ __forceinline__ void frag_from_acc(u32 (&af)[16], const float (&acc)[8][4],
        const float* __restrict__ bias, int tg, bool do_elu) {
    #pragma unroll
    for (int ks = 0; ks < 4; ks++) {
        int c = ks * 16 + tg * 2, c8 = c + 8;
        float b0 = bias[c], b1 = bias[c + 1], b2 = bias[c8], b3 = bias[c8 + 1];
        float v00 = acc[2 * ks][0] + b0, v01 = acc[2 * ks][1] + b1;
        float v10 = acc[2 * ks][2] + b0, v11 = acc[2 * ks][3] + b1;
        float w00 = acc[2 * ks + 1][0] + b2, w01 = acc[2 * ks + 1][1] + b3;
        float w10 = acc[2 * ks + 1][2] + b2, w11 = acc[2 * ks + 1][3] + b3;
        if (do_elu) {
            v00 = eluf_(v00); v01 = eluf_(v01); v10 = eluf_(v10); v11 = eluf_(v11);
            w00 = eluf_(w00); w01 = eluf_(w01); w10 = eluf_(w10); w11 = eluf_(w11);
        }
        af[4 * ks]     = pack_bf2(v00, v01);   // row g,   k c,c+1
        af[4 * ks + 1] = pack_bf2(v10, v11);   // row g+8
        af[4 * ks + 2] = pack_bf2(w00, w01);   // row g,   k c8,c8+1
        af[4 * ks + 3] = pack_bf2(w10, w11);   // row g+8
    }
}

// ============================================================
// kPrepW: transpose + split weight B-operands into interleaved [n][k] images
// ============================================================
__device__ __forceinline__ void store8hl_p(__nv_bfloat16* hiA, __nv_bfloat16* loA,
                                           size_t rowbase, int j, const float f[8]) {
    int base = (j >> 1) * 16 + ((j & 1) << 1);
    #pragma unroll
    for (int p = 0; p < 4; p++) {
        u32 h, l;
        split2(f[2 * p], f[2 * p + 1], h, l);
        *(u32*)&hiA[rowbase + base + 4 * p] = h;
        *(u32*)&loA[rowbase + base + 4 * p] = l;
    }
}
__device__ __forceinline__ void store8h_p(__nv_bfloat16* hiA, size_t rowbase, int j,
                                          const float f[8]) {
    int base = (j >> 1) * 16 + ((j & 1) << 1);
    #pragma unroll
    for (int p = 0; p < 4; p++)
        *(u32*)&hiA[rowbase + base + 4 * p] = pack_bf2(f[2 * p], f[2 * p + 1]);
}

__global__ void __launch_bounds__(256) kPrepW(
    const float* __restrict__ wgW1, const float* __restrict__ wgWs,
    const float* __restrict__ vW1, const float* __restrict__ vW2,
    const float* __restrict__ vWg) {
    int id = blockIdx.x * 256 + threadIdx.x;
    float f[8];
    if (id < 16384) {                    // wgB: [64 n][2048 k] hi/lo
        int j = id & 7, n = (id >> 3) & 63, c = id >> 9;
        int k0 = c * 64 + j * 8;
        #pragma unroll
        for (int kk = 0; kk < 8; kk++)
            f[kk] = (n < 32) ? wgW1[(size_t)(k0 + kk) * 32 + n]
                             : wgWs[(size_t)(k0 + kk) * 32 + (n - 32)];
        store8hl_p(g_wgBh, g_wgBl, (size_t)n * 2048 + c * 64, j, f);
    } else if (id < 32768) {             // vW1: [v][64 n][64 k]
        id -= 16384;
        int j = id & 7, n = (id >> 3) & 63, v = id >> 9;
        #pragma unroll
        for (int kk = 0; kk < 8; kk++)
            f[kk] = vW1[((size_t)v * 64 + j * 8 + kk) * 64 + n];
        store8h_p(g_w1Bh, ((size_t)v * 64 + n) * 64, j, f);
    } else if (id < 49152) {             // vW2
        id -= 32768;
        int j = id & 7, n = (id >> 3) & 63, v = id >> 9;
        #pragma unroll
        for (int kk = 0; kk < 8; kk++)
            f[kk] = vW2[((size_t)v * 64 + j * 8 + kk) * 64 + n];
        store8h_p(g_w2Bh, ((size_t)v * 64 + n) * 64, j, f);
    } else if (id < 81920) {             // vWg: [v][128 n][64 k]
        id -= 49152;
        int j = id & 7, n = (id >> 3) & 127, v = id >> 10;
        #pragma unroll
        for (int kk = 0; kk < 8; kk++)
            f[kk] = vWg[((size_t)v * 64 + j * 8 + kk) * 128 + n];
        store8h_p(g_wgB2h, ((size_t)v * 128 + n) * 64, j, f);
    }
}

// ============================================================
// kA1m: Y[N,64] = flat[N,2048] @ [W1|Ws] (+bias) via mma.sync (3-term).
// x staged as raw fp32 via cp.async; hi/lo A-fragments built in-loop.
// ============================================================
#define A1_X   0
#define A1_BH  36864
#define A1_BL  47104
#define A1_SMEM 57344

__global__ void __launch_bounds__(256, 2) kA1m(
    const float* __restrict__ x, const float* __restrict__ b1,
    const float* __restrict__ bs) {
    extern __shared__ __align__(16) char sm[];
    const int tid = threadIdx.x, lane = tid & 31;
    const int warp = tid >> 5, g = lane >> 2, tg = lane & 3;
    const int r0 = warp * 16, tok0 = blockIdx.x * 128;

    float acc[8][4];
    #pragma unroll
    for (int nt = 0; nt < 8; nt++)
        acc[nt][0] = acc[nt][1] = acc[nt][2] = acc[nt][3] = 0.f;

    for (int kc = 0; kc < 32; kc++) {
        stage_w64_a(sm, A1_BH, g_wgBh + kc * 64, 2048, tid);
        stage_w64_a(sm, A1_BL, g_wgBl + kc * 64, 2048, tid);
        stage_xf32(sm, A1_X, x, tok0, kc * 64, tid);
        cp_commit_wait();
        __syncthreads();
        gemm3x<8>(sm, A1_X, A1_BH, A1_BL, r0, g, tg, acc);
        __syncthreads();
    }

    #pragma unroll
    for (int nt = 0; nt < 8; nt++) {
        int c = nt * 8 + tg * 2;
        float bb0 = (c < 32) ? b1[c] : bs[c - 32];
        float bb1 = (c + 1 < 32) ? b1[c + 1] : bs[c + 1 - 32];
        float* yA = &g_y[(size_t)(tok0 + r0 + g) * 64 + c];
        float* yB = &g_y[(size_t)(tok0 + r0 + g + 8) * 64 + c];
        yA[0] = acc[nt][0] + bb0; yA[1] = acc[nt][1] + bb1;
        yB[0] = acc[nt][2] + bb0; yB[1] = acc[nt][3] + bb1;
    }
}

// ============================================================
// kA2: per-token tail of the weight GRN (fp32, cheap)
// ============================================================
__global__ void __launch_bounds__(256) kA2(
    const float* __restrict__ W2, const float* __restrict__ b2,
    const float* __restrict__ Wg, const float* __restrict__ bg,
    const float* __restrict__ gam, const float* __restrict__ bet, int N) {
    __shared__ float W2s[32 * 33];
    __shared__ float Wgs[32 * 64];
    const int tid = threadIdx.x;
    for (int i = tid; i < 1024; i += 256) W2s[(i >> 5) * 33 + (i & 31)] = W2[i];
    for (int i = tid; i < 2048; i += 256) Wgs[i] = Wg[i];
    __syncthreads();

    const int lane = tid & 31, warp = tid >> 5;
    const int tok = blockIdx.x * 8 + warp;
    if (tok >= N) return;

    const float* y = &g_y[(size_t)tok * 64];
    float h = eluf_(y[lane]);
    float skip = y[32 + lane];

    float t = b2[lane];
    #pragma unroll
    for (int i = 0; i < 32; i++)
        t = fmaf(__shfl_sync(0xffffffffu, h, i), W2s[i * 33 + lane], t);

    float ga = bg[lane], gb = bg[32 + lane];
    #pragma unroll
    for (int i = 0; i < 32; i++) {
        float tv = __shfl_sync(0xffffffffu, t, i);
        ga = fmaf(tv, Wgs[i * 64 + lane], ga);
        gb = fmaf(tv, Wgs[i * 64 + 32 + lane], gb);
    }

    float z = skip + ga * sigmoidf_(gb);
    float m = wsum_(z) * (1.f / 32.f);
    float d = z - m;
    float var = wsum_(d * d) * (1.f / 32.f);
    float zn = d * rsqrtf(var + 1e-5f) * gam[lane] + bet[lane];

    float mx = wmax_(zn);
    float e = __expf(zn - mx);
    float se = wsum_(e);
    g_w[(size_t)tok * VD + lane] = e / se;
}

// ============================================================
// kBm: per-variable GRNs + combine. Register-chained GEMMs (2 syncs/var),
//      x staged as raw fp32 (cp.async); GEMM1 A-frags built in-loop;
//      epilogue reads exact fp32 x from smem.
// ============================================================
#define KB_X    0
#define KB_W1   36864
#define KB_W2   47104
#define KB_WG   57344
#define KB_BIAS 77824
#define KB_SMEM (77824 + 2048)

__global__ void __launch_bounds__(256, 2) kBm(
    const float* __restrict__ x,
    const float* __restrict__ vb1, const float* __restrict__ vb2,
    const float* __restrict__ vbg, const float* __restrict__ vgam,
    const float* __restrict__ vbet, float* __restrict__ out) {
    extern __shared__ __align__(16) char sm[];
    float* b1s  = (float*)(sm + KB_BIAS);        // 64
    float* b2s  = b1s + 64;                      // 64
    float* bgs  = b2s + 64;                      // 128
    float* gams = bgs + 128;                     // 64
    float* bets = gams + 64;                     // 64
    float* wvS  = bets + 64;                     // 128

    const int tid = threadIdx.x, lane = tid & 31;
    const int warp = tid >> 5, g = lane >> 2, tg = lane & 3;
    const int r0 = warp * 16, tok0 = blockIdx.x * 128;

    float oacc[2][16];
    #pragma unroll
    for (int s = 0; s < 2; s++)
        #pragma unroll
        for (int i = 0; i < 16; i++) oacc[s][i] = 0.f;

    for (int v = 0; v < VD; v++) {
        // ---- stage (everything via cp.async) ----
        stage_w64_a(sm, KB_W1, g_w1Bh + (size_t)v * 4096, 64, tid);
        stage_w64_a(sm, KB_W2, g_w2Bh + (size_t)v * 4096, 64, tid);
        stage_w128_a(sm, KB_WG, g_wgB2h + (size_t)v * 8192, tid);
        stage_xf32(sm, KB_X, x, tok0, v * 64, tid);
        if (tid < 64) {
            b1s[tid]  = vb1[(size_t)v * 64 + tid];
            b2s[tid]  = vb2[(size_t)v * 64 + tid];
            gams[tid] = vgam[(size_t)v * 64 + tid];
            bets[tid] = vbet[(size_t)v * 64 + tid];
        } else if (tid < 192) {
            bgs[tid - 64] = vbg[(size_t)v * 128 + (tid - 64)];
        }
        if (tid < 128) wvS[tid] = g_w[(size_t)(tok0 + tid) * VD + v];
        cp_commit_wait();
        __syncthreads();

        // ---- GEMM1: X@W1 -> elu(+b1) -> register fragments ----
        u32 hf[16];
        {
            float acc[8][4];
            #pragma unroll
            for (int nt = 0; nt < 8; nt++)
                acc[nt][0] = acc[nt][1] = acc[nt][2] = acc[nt][3] = 0.f;
            gemm1x<8>(sm, KB_X, KB_W1, r0, g, tg, acc);
            frag_from_acc(hf, acc, b1s, tg, true);
        }

        // ---- GEMM2: H1@W2 (+b2) -> register fragments ----
        {
            float acc[8][4];
            #pragma unroll
            for (int nt = 0; nt < 8; nt++)
                acc[nt][0] = acc[nt][1] = acc[nt][2] = acc[nt][3] = 0.f;
            gemmR<8>(sm, KB_W2, hf, g, tg, acc);
            frag_from_acc(hf, acc, b2s, tg, false);
        }

        // ---- GEMM3: H2@Wg (N=128) + epilogue (exact fp32 x from smem) ----
        {
            float acc3[16][4];
            #pragma unroll
            for (int nt = 0; nt < 16; nt++)
                acc3[nt][0] = acc3[nt][1] = acc3[nt][2] = acc3[nt][3] = 0.f;
            gemmR<16>(sm, KB_WG, hf, g, tg, acc3);

            const float* xb = (const float*)(sm + KB_X);
            #pragma unroll
            for (int sel = 0; sel < 2; sel++) {
                const int row = r0 + g + sel * 8;
                const int di = sel * 2;
                float vals[16];
                float s1 = 0.f, s2 = 0.f;
                #pragma unroll
                for (int i = 0; i < 8; i++) {
                    int c = i * 8 + tg * 2;
                    float2 xv = *(const float2*)&xb[row * LDX + c];
                    float aL = acc3[i][di] + bgs[c];
                    float aR = acc3[i][di + 1] + bgs[c + 1];
                    float gL = acc3[8 + i][di] + bgs[64 + c];
                    float gR = acc3[8 + i][di + 1] + bgs[64 + c + 1];
                    float v0 = xv.x + aL * sigmoidf_(gL);
                    float v1 = xv.y + aR * sigmoidf_(gR);
                    vals[2 * i] = v0; vals[2 * i + 1] = v1;
                    s1 += v0 + v1;
                    s2 += v0 * v0 + v1 * v1;
                }
                s1 += __shfl_xor_sync(0xffffffffu, s1, 1);
                s1 += __shfl_xor_sync(0xffffffffu, s1, 2);
                s2 += __shfl_xor_sync(0xffffffffu, s2, 1);
                s2 += __shfl_xor_sync(0xffffffffu, s2, 2);
                float m = s1 * (1.f / 64.f);
                float var = fmaxf(s2 * (1.f / 64.f) - m * m, 0.f);
                float rs = rsqrtf(var + 1e-5f);
                float wv = wvS[row];
                #pragma unroll
                for (int i = 0; i < 8; i++) {
                    int c = i * 8 + tg * 2;
                    float pv0 = (vals[2 * i] - m) * rs * gams[c] + bets[c];
                    float pv1 = (vals[2 * i + 1] - m) * rs * gams[c + 1] + bets[c + 1];
                    oacc[sel][2 * i]     = fmaf(wv, pv0, oacc[sel][2 * i]);
                    oacc[sel][2 * i + 1] = fmaf(wv, pv1, oacc[sel][2 * i + 1]);
                }
            }
        }
        __syncthreads();   // done reading tiles before next stage overwrites
    }

    #pragma unroll
    for (int sel = 0; sel < 2; sel++) {
        int row = r0 + g + sel * 8;
        float* op = &out[(size_t)(tok0 + row) * 64];
        #pragma unroll
        for (int i = 0; i < 8; i++) {
            int c = i * 8 + tg * 2;
            *(float2*)&op[c] = make_float2(oacc[sel][2 * i], oacc[sel][2 * i + 1]);
        }
    }
}

// ============================================================
extern "C" void kernel_launch(void* const* d_in, const int* in_sizes, int n_in,
                              void* d_out, int out_size) {
    const float* x     = (const float*)d_in[0];
    const float* wgW1  = (const float*)d_in[1];
    const float* wgb1  = (const float*)d_in[2];
    const float* wgW2  = (const float*)d_in[3];
    const float* wgb2  = (const float*)d_in[4];
    const float* wgWg  = (const float*)d_in[5];
    const float* wgbg  = (const float*)d_in[6];
    const float* wgWs  = (const float*)d_in[7];
    const float* wgbs  = (const float*)d_in[8];
    const float* wggam = (const float*)d_in[9];
    const float* wgbet = (const float*)d_in[10];
    const float* vW1   = (const float*)d_in[11];
    const float* vb1   = (const float*)d_in[12];
    const float* vW2   = (const float*)d_in[13];
    const float* vb2   = (const float*)d_in[14];
    const float* vWg   = (const float*)d_in[15];
    const float* vbg   = (const float*)d_in[16];
    const float* vgam  = (const float*)d_in[17];
    const float* vbet  = (const float*)d_in[18];
    float* out = (float*)d_out;

    int N = in_sizes[0] / KF;  // 32768

    kPrepW<<<320, 256>>>(wgW1, wgWs, vW1, vW2, vWg);

    cudaFuncSetAttribute(kA1m, cudaFuncAttributeMaxDynamicSharedMemorySize, A1_SMEM);
    kA1m<<<N / 128, 256, A1_SMEM>>>(x, wgb1, wgbs);

    kA2<<<(N + 7) / 8, 256>>>(wgW2, wgb2, wgWg, wgbg, wggam, wgbet, N);

    cudaFuncSetAttribute(kBm, cudaFuncAttributeMaxDynamicSharedMemorySize, KB_SMEM);
    kBm<<<N / 128, 256, KB_SMEM>>>(x, vb1, vb2, vbg, vgam, vbet, out);
}